// round 6
// baseline (speedup 1.0000x reference)
#include <cuda_runtime.h>
#include <math.h>
#include <stdint.h>

#define kB 64
#define kT 128
#define kU 256
#define kV 16000
#define kG 1024   /* 4*U */
#define kM 8192   /* B*T */
#define kK2 512   /* 2*U */

// ---------------- scratch (device globals; no allocation allowed) ----------
__device__ __align__(16) float g_Z0x[kT * kB * kG];
__device__ __align__(16) float g_H0[(kT + 1) * kB * kU];
__device__ __align__(16) float g_H1[(kT + 1) * kB * kU];
__device__ __align__(16) float g_Wt0[kG * kK2];   // full transpose [col][k]
__device__ __align__(16) float g_Wt1[kG * kK2];
__device__ float g_S[kM];
__device__ float g_TL[kM];
__device__ unsigned g_bar[4];

__device__ __forceinline__ float sigmoidf_(float x) { return 1.f / (1.f + __expf(-x)); }

__device__ __forceinline__ uint32_t f2tf32(float x) {
    uint32_t u; asm("cvt.rna.tf32.f32 %0, %1;" : "=r"(u) : "f"(x)); return u;
}

#define FMA2(acc, a, b) \
    asm("fma.rn.f32x2 %0, %1, %2, %0;" : "+l"(acc) : "l"(a), "l"(b))

// ---------------- init: zero states + sums + barriers -----------------------
__global__ void k_init() {
    int i = blockIdx.x * 256 + threadIdx.x;
    if (i < kB * kU) { g_H0[i] = 0.f; g_H1[i] = 0.f; }
    if (i < kM) g_S[i] = 0.f;
    if (i < 4) g_bar[i] = 0u;
}

// ---------------- full transpose of both W: Wt[col][k] = W[k][col] ---------
__global__ void k_transpose(const float* __restrict__ W0, const float* __restrict__ W1) {
    __shared__ float tile[32][33];
    const float* W = blockIdx.z ? W1 : W0;
    float* Wt = blockIdx.z ? g_Wt1 : g_Wt0;
    int col0 = blockIdx.x * 32, k0 = blockIdx.y * 32;
#pragma unroll
    for (int i = threadIdx.y; i < 32; i += 8)
        tile[i][threadIdx.x] = W[(size_t)(k0 + i) * kG + col0 + threadIdx.x];
    __syncthreads();
#pragma unroll
    for (int i = threadIdx.y; i < 32; i += 8)
        Wt[(size_t)(col0 + i) * kK2 + k0 + threadIdx.x] = tile[threadIdx.x][i];
}

// ---------------- Zx GEMM (tf32 mma, staged cvt): Z0 = emb[idx] @ W0x + b0 --
__global__ __launch_bounds__(512) void k_gemm_zx_tf32(
    const int* __restrict__ input_data, const float* __restrict__ emb,
    const float* __restrict__ W, const float* __restrict__ bias) {
    extern __shared__ uint32_t sm[];
    uint32_t* As = sm;                   // 2 buffers of 256x36 (tf32 bits)
    uint32_t* Bs = sm + 2 * 256 * 36;    // 2 buffers of 32x136
    __shared__ const float* rowp[256];
    float* Z = g_Z0x;
    const int tid = threadIdx.x;
    const int lane = tid & 31;
    const int w = tid >> 5;
    const int warpM = w & 7;
    const int warpN = w >> 3;
    const int m0 = blockIdx.y * 256;
    const int n0 = blockIdx.x * 128;
    const int r = lane >> 2, cq = lane & 3;

    if (tid < 256) {
        int m = m0 + tid;
        int t = m >> 6, b = m & 63;
        rowp[tid] = emb + (size_t)input_data[b * kT + t] * kU;
    }
    __syncthreads();

    float acc[2][8][4];
#pragma unroll
    for (int i = 0; i < 2; i++)
#pragma unroll
        for (int j = 0; j < 8; j++)
#pragma unroll
            for (int k = 0; k < 4; k++) acc[i][j][k] = 0.f;

    float4 ra[4], rb[2];
    auto loadG = [&](int kc) {
#pragma unroll
        for (int p = 0; p < 4; p++) {
            int e = p * 512 + tid;
            ra[p] = *(const float4*)&rowp[e >> 3][kc * 32 + (e & 7) * 4];
        }
#pragma unroll
        for (int p = 0; p < 2; p++) {
            int e = p * 512 + tid;
            rb[p] = *(const float4*)&W[(size_t)(kc * 32 + (e >> 5)) * kG + n0 + (e & 31) * 4];
        }
    };
    auto storeS = [&](int buf) {
        uint32_t* Ab = As + buf * 256 * 36;
        uint32_t* Bb = Bs + buf * 32 * 136;
#pragma unroll
        for (int p = 0; p < 4; p++) {
            int e = p * 512 + tid;
            uint4 v = make_uint4(f2tf32(ra[p].x), f2tf32(ra[p].y), f2tf32(ra[p].z), f2tf32(ra[p].w));
            *(uint4*)&Ab[(e >> 3) * 36 + (e & 7) * 4] = v;
        }
#pragma unroll
        for (int p = 0; p < 2; p++) {
            int e = p * 512 + tid;
            uint4 v = make_uint4(f2tf32(rb[p].x), f2tf32(rb[p].y), f2tf32(rb[p].z), f2tf32(rb[p].w));
            *(uint4*)&Bb[(e >> 5) * 136 + (e & 31) * 4] = v;
        }
    };

    loadG(0);
    storeS(0);
    __syncthreads();

    for (int kc = 0; kc < 8; kc++) {
        int buf = kc & 1;
        if (kc < 7) loadG(kc + 1);
        const uint32_t* Ab = As + buf * 256 * 36;
        const uint32_t* Bb = Bs + buf * 32 * 136;
#pragma unroll
        for (int kk = 0; kk < 4; kk++) {
            uint32_t af[2][4];
#pragma unroll
            for (int mi = 0; mi < 2; mi++) {
                const uint32_t* ap = &Ab[(warpM * 32 + mi * 16 + r) * 36 + kk * 8 + cq];
                af[mi][0] = ap[0];
                af[mi][1] = ap[8 * 36];
                af[mi][2] = ap[4];
                af[mi][3] = ap[8 * 36 + 4];
            }
#pragma unroll
            for (int ni = 0; ni < 8; ni++) {
                const uint32_t* bp = &Bb[(kk * 8 + cq) * 136 + warpN * 64 + ni * 8 + r];
                uint32_t b0 = bp[0];
                uint32_t b1 = bp[4 * 136];
#pragma unroll
                for (int mi = 0; mi < 2; mi++) {
                    asm volatile(
                        "mma.sync.aligned.m16n8k8.row.col.f32.tf32.tf32.f32 "
                        "{%0,%1,%2,%3}, {%4,%5,%6,%7}, {%8,%9}, {%0,%1,%2,%3};\n"
                        : "+f"(acc[mi][ni][0]), "+f"(acc[mi][ni][1]),
                          "+f"(acc[mi][ni][2]), "+f"(acc[mi][ni][3])
                        : "r"(af[mi][0]), "r"(af[mi][1]), "r"(af[mi][2]), "r"(af[mi][3]),
                          "r"(b0), "r"(b1));
                }
            }
        }
        if (kc < 7) { storeS(buf ^ 1); __syncthreads(); }
    }

#pragma unroll
    for (int ni = 0; ni < 8; ni++) {
        int col = n0 + warpN * 64 + ni * 8 + cq * 2;
        float2 bb = *(const float2*)&bias[col];
#pragma unroll
        for (int mi = 0; mi < 2; mi++) {
            int gm = m0 + warpM * 32 + mi * 16 + r;
            *(float2*)&Z[(size_t)gm * kG + col] =
                make_float2(acc[mi][ni][0] + bb.x, acc[mi][ni][1] + bb.y);
            *(float2*)&Z[(size_t)(gm + 8) * kG + col] =
                make_float2(acc[mi][ni][2] + bb.x, acc[mi][ni][3] + bb.y);
        }
    }
}

// ---------------- pipelined 2-layer persistent LSTM -------------------------
// 128 blocks = 4 row-groups (16 rows) x 32 u-blocks (8 u). Iteration t:
//   compute h0[t+1] (from smem h0[t] + precomputed z0x[t])
//   compute h1[t]   (z1 = [h0[t]; h1[t-1]] @ W1 + b1, on the fly)
// barrier over 32 blocks per row-group; reload h0[t+1], h1[t] into smem.
// Thread: warp w -> (u = w&7, row-half = w>>3); lane -> (r8, gp, kh).
__global__ __launch_bounds__(512) void k_lstm_pipe(const float* __restrict__ b1v) {
    extern __shared__ float sms[];
    float* w0s = sms;                    // 32 rows x 264 (segs at 0,136)
    float* w1s = w0s + 32 * 264;         // 32 rows x 540 (segs at 0,136,272,408)
    float* h0s = w1s + 32 * 540;         // 16 rows x 260 (segs at 0,132)
    float* h1s = h0s + 16 * 260;         // 16 rows x 260

    const int tid = threadIdx.x;
    const int bx = blockIdx.x;
    const int rg = bx >> 5, ub = bx & 31;
    const int r0 = rg * 16, u0 = ub * 8;

    // ---- load weight slices (once) ----
    {
        const float4* s0 = (const float4*)g_Wt0;   // row col, 128 f4 (k 0..511)
        const float4* s1 = (const float4*)g_Wt1;
#pragma unroll
        for (int p = 0; p < 4; p++) {              // W0 h-part: 32 rows x 64 f4
            int e = p * 512 + tid;
            int zr = e >> 6, kf = e & 63;
            int g = zr & 3, uq = zr >> 2;
            *(float4*)&w0s[zr * 264 + kf * 4 + ((kf >> 5) << 3)] =
                s0[(size_t)(g * kU + u0 + uq) * 128 + 64 + kf];
        }
#pragma unroll
        for (int p = 0; p < 8; p++) {              // W1 full: 32 rows x 128 f4
            int e = p * 512 + tid;
            int zr = e >> 7, kf = e & 127;
            int g = zr & 3, uq = zr >> 2;
            *(float4*)&w1s[zr * 540 + kf * 4 + ((kf >> 5) << 3)] =
                s1[(size_t)(g * kU + u0 + uq) * 128 + kf];
        }
    }
    // ---- zero h smem (initial state) ----
#pragma unroll
    for (int p = 0; p < 2; p++) {
        int e = p * 512 + tid;
        int row = e >> 6, kf = e & 63;
        int off = row * 260 + kf * 4 + ((kf >> 5) << 2);
        *(float4*)&h0s[off] = make_float4(0.f, 0.f, 0.f, 0.f);
        *(float4*)&h1s[off] = make_float4(0.f, 0.f, 0.f, 0.f);
    }
    __syncthreads();

    const int w = tid >> 5, lane = tid & 31;
    const int uu = w & 7, rh = w >> 3;
    const int r8 = lane >> 2, gp = (lane >> 1) & 1, kh = lane & 1;
    const int r = rh * 8 + r8;
    const int u = u0 + uu;
    const int g0 = 2 * gp, g1 = g0 + 1;

    const ulonglong2* h0p = (const ulonglong2*)&h0s[r * 260 + kh * 132];
    const ulonglong2* w0a = (const ulonglong2*)&w0s[(g0 + 4 * uu) * 264 + kh * 136];
    const ulonglong2* w0b = (const ulonglong2*)&w0s[(g1 + 4 * uu) * 264 + kh * 136];
    const ulonglong2* x1p = (const ulonglong2*)&(kh ? h1s : h0s)[r * 260];
    const ulonglong2* w1a = (const ulonglong2*)&w1s[(g0 + 4 * uu) * 540 + kh * 272];
    const ulonglong2* w1b = (const ulonglong2*)&w1s[(g1 + 4 * uu) * 540 + kh * 272];
    const float* zbase = g_Z0x + (size_t)(r0 + r) * kG + u;
    float* hdst0 = g_H0 + (size_t)(r0 + r) * kU + u;
    float* hdst1 = g_H1 + (size_t)(r0 + r) * kU + u;
    const float b1a = b1v[g0 * kU + u];
    const float b1b = b1v[g1 * kU + u];

    float c0 = 0.f, c1 = 0.f;
    float lo, hi;

    for (int t = 0; t <= kT; t++) {
        // ---- layer 0 step t (t < kT) ----
        if (t < kT) {
            const float* z = zbase + (size_t)t * kB * kG;
            float z0r = __ldg(z + g0 * kU);
            float z1r = __ldg(z + g1 * kU);

            unsigned long long a0 = 0ull, a1 = 0ull;
#pragma unroll
            for (int k = 0; k < 32; k++) {          // K-half = 128 floats = 32 f4
                ulonglong2 hv = h0p[k];
                ulonglong2 va = w0a[k], vb = w0b[k];
                FMA2(a0, hv.x, va.x); FMA2(a1, hv.x, vb.x);
                FMA2(a0, hv.y, va.y); FMA2(a1, hv.y, vb.y);
            }
            asm("mov.b64 {%0,%1}, %2;" : "=f"(lo), "=f"(hi) : "l"(a0));
            float s0 = lo + hi;
            asm("mov.b64 {%0,%1}, %2;" : "=f"(lo), "=f"(hi) : "l"(a1));
            float s1 = lo + hi;
            s0 += __shfl_xor_sync(0xffffffffu, s0, 1);   // combine K halves
            s1 += __shfl_xor_sync(0xffffffffu, s1, 1);
            float za = z0r + s0, zb = z1r + s1;

            float send = 0.f, ff = 0.f, oo = 0.f;
            if (gp == 0) {
                send = sigmoidf_(za) * tanhf(zb);        // sigmoid(i)*tanh(j)
            } else {
                ff = sigmoidf_(za + 1.f);                // FORGET_BIAS = 1
                oo = sigmoidf_(zb);
            }
            float ig = __shfl_xor_sync(0xffffffffu, send, 2);
            if (gp == 1) {
                c0 = c0 * ff + ig;
                if (kh == 0)
                    hdst0[(size_t)(t + 1) * kB * kU] = tanhf(c0) * oo;
            }
        }
        // ---- layer 1 step t-1 (t >= 1): z1 = [h0[t]; h1[t-1]] @ W1 + b1 ----
        if (t >= 1) {
            unsigned long long a0 = 0ull, a1 = 0ull;
#pragma unroll
            for (int k = 0; k < 32; k++) {          // seg 0: 128 floats
                ulonglong2 hv = x1p[k];
                ulonglong2 va = w1a[k], vb = w1b[k];
                FMA2(a0, hv.x, va.x); FMA2(a1, hv.x, vb.x);
                FMA2(a0, hv.y, va.y); FMA2(a1, hv.y, vb.y);
            }
#pragma unroll
            for (int k = 0; k < 32; k++) {          // seg 1: next 128 floats
                ulonglong2 hv = x1p[33 + k];
                ulonglong2 va = w1a[34 + k], vb = w1b[34 + k];
                FMA2(a0, hv.x, va.x); FMA2(a1, hv.x, vb.x);
                FMA2(a0, hv.y, va.y); FMA2(a1, hv.y, vb.y);
            }
            asm("mov.b64 {%0,%1}, %2;" : "=f"(lo), "=f"(hi) : "l"(a0));
            float s0 = lo + hi;
            asm("mov.b64 {%0,%1}, %2;" : "=f"(lo), "=f"(hi) : "l"(a1));
            float s1 = lo + hi;
            s0 += __shfl_xor_sync(0xffffffffu, s0, 1);   // x-part + h-part
            s1 += __shfl_xor_sync(0xffffffffu, s1, 1);
            float za = b1a + s0, zb = b1b + s1;

            float send = 0.f, ff = 0.f, oo = 0.f;
            if (gp == 0) {
                send = sigmoidf_(za) * tanhf(zb);
            } else {
                ff = sigmoidf_(za + 1.f);
                oo = sigmoidf_(zb);
            }
            float ig = __shfl_xor_sync(0xffffffffu, send, 2);
            if (gp == 1) {
                c1 = c1 * ff + ig;
                if (kh == 0)
                    hdst1[(size_t)t * kB * kU] = tanhf(c1) * oo;
            }
        }
        // ---- barrier + reload (not after final iteration) ----
        if (t < kT) {
            __syncthreads();
            if (tid == 0) {
                asm volatile("red.release.gpu.global.add.u32 [%0], %1;"
                             :: "l"(&g_bar[rg]), "r"(1u) : "memory");
                unsigned goal = (unsigned)(t + 1) * 32u;
                unsigned v;
                do {
                    asm volatile("ld.acquire.gpu.u32 %0, [%1];" : "=r"(v) : "l"(&g_bar[rg]));
                } while (v < goal);
            }
            __syncthreads();
            const float4* s0g = (const float4*)(g_H0 + (size_t)(t + 1) * kB * kU + (size_t)r0 * kU);
            const float4* s1g = (const float4*)(g_H1 + (size_t)t * kB * kU + (size_t)r0 * kU);
#pragma unroll
            for (int p = 0; p < 2; p++) {
                int e = p * 512 + tid;
                int row = e >> 6, kf = e & 63;
                int off = row * 260 + kf * 4 + ((kf >> 5) << 2);
                *(float4*)&h0s[off] = s0g[row * 64 + kf];
                *(float4*)&h1s[off] = s1g[row * 64 + kf];
            }
            __syncthreads();
        }
    }
}

// ---------------- fused logits GEMM (tf32 mma, staged cvt) -----------------
__global__ __launch_bounds__(512) void k_logits_tf32(
    const int* __restrict__ targets, const float* __restrict__ SW,
    const float* __restrict__ sb) {
    extern __shared__ uint32_t sm[];
    uint32_t* As = sm;                   // 2 buffers of 256x36
    uint32_t* Bs = sm + 2 * 256 * 36;    // 2 buffers of 32x136
    const float* __restrict__ A = g_H1 + kB * kU;
    const int tid = threadIdx.x;
    const int lane = tid & 31;
    const int w = tid >> 5;
    const int warpM = w & 7;
    const int warpN = w >> 3;
    const int m0 = blockIdx.y * 256;
    const int n0 = blockIdx.x * 128;
    const int r = lane >> 2, cq = lane & 3;

    float acc[2][8][4];
#pragma unroll
    for (int i = 0; i < 2; i++)
#pragma unroll
        for (int j = 0; j < 8; j++)
#pragma unroll
            for (int k = 0; k < 4; k++) acc[i][j][k] = 0.f;

    float4 ra[4], rb[2];
    auto loadG = [&](int kc) {
#pragma unroll
        for (int p = 0; p < 4; p++) {
            int e = p * 512 + tid;
            ra[p] = *(const float4*)&A[(size_t)(m0 + (e >> 3)) * kU + kc * 32 + (e & 7) * 4];
        }
#pragma unroll
        for (int p = 0; p < 2; p++) {
            int e = p * 512 + tid;
            rb[p] = *(const float4*)&SW[(size_t)(kc * 32 + (e >> 5)) * kV + n0 + (e & 31) * 4];
        }
    };
    auto storeS = [&](int buf) {
        uint32_t* Ab = As + buf * 256 * 36;
        uint32_t* Bb = Bs + buf * 32 * 136;
#pragma unroll
        for (int p = 0; p < 4; p++) {
            int e = p * 512 + tid;
            uint4 v = make_uint4(f2tf32(ra[p].x), f2tf32(ra[p].y), f2tf32(ra[p].z), f2tf32(ra[p].w));
            *(uint4*)&Ab[(e >> 3) * 36 + (e & 7) * 4] = v;
        }
#pragma unroll
        for (int p = 0; p < 2; p++) {
            int e = p * 512 + tid;
            uint4 v = make_uint4(f2tf32(rb[p].x), f2tf32(rb[p].y), f2tf32(rb[p].z), f2tf32(rb[p].w));
            *(uint4*)&Bb[(e >> 5) * 136 + (e & 31) * 4] = v;
        }
    };

    loadG(0);
    storeS(0);
    __syncthreads();

    for (int kc = 0; kc < 8; kc++) {
        int buf = kc & 1;
        if (kc < 7) loadG(kc + 1);
        const uint32_t* Ab = As + buf * 256 * 36;
        const uint32_t* Bb = Bs + buf * 32 * 136;
#pragma unroll
        for (int kk = 0; kk < 4; kk++) {
            uint32_t af[2][4];
#pragma unroll
            for (int mi = 0; mi < 2; mi++) {
                const uint32_t* ap = &Ab[(warpM * 32 + mi * 16 + r) * 36 + kk * 8 + cq];
                af[mi][0] = ap[0];
                af[mi][1] = ap[8 * 36];
                af[mi][2] = ap[4];
                af[mi][3] = ap[8 * 36 + 4];
            }
#pragma unroll
            for (int ni = 0; ni < 8; ni++) {
                const uint32_t* bp = &Bb[(kk * 8 + cq) * 136 + warpN * 64 + ni * 8 + r];
                uint32_t b0 = bp[0];
                uint32_t b1 = bp[4 * 136];
#pragma unroll
                for (int mi = 0; mi < 2; mi++) {
                    asm volatile(
                        "mma.sync.aligned.m16n8k8.row.col.f32.tf32.tf32.f32 "
                        "{%0,%1,%2,%3}, {%4,%5,%6,%7}, {%8,%9}, {%0,%1,%2,%3};\n"
                        : "+f"(acc[mi][ni][0]), "+f"(acc[mi][ni][1]),
                          "+f"(acc[mi][ni][2]), "+f"(acc[mi][ni][3])
                        : "r"(af[mi][0]), "r"(af[mi][1]), "r"(af[mi][2]), "r"(af[mi][3]),
                          "r"(b0), "r"(b1));
                }
            }
        }
        if (kc < 7) { storeS(buf ^ 1); __syncthreads(); }
    }

#pragma unroll
    for (int mi = 0; mi < 2; mi++) {
#pragma unroll
        for (int hh = 0; hh < 2; hh++) {
            int gm = m0 + warpM * 32 + mi * 16 + r + 8 * hh;
            int tt = gm >> 6, bb = gm & 63;
            int tg = targets[bb * kT + tt];
            float s = 0.f;
#pragma unroll
            for (int ni = 0; ni < 8; ni++) {
                int col = n0 + warpN * 64 + ni * 8 + cq * 2;
                float l0 = acc[mi][ni][hh * 2 + 0] + sb[col];
                float l1 = acc[mi][ni][hh * 2 + 1] + sb[col + 1];
                if (col == tg) g_TL[gm] = l0;
                if (col + 1 == tg) g_TL[gm] = l1;
                s += __expf(l0) + __expf(l1);
            }
            s += __shfl_xor_sync(0xffffffffu, s, 1);
            s += __shfl_xor_sync(0xffffffffu, s, 2);
            if (cq == 0) atomicAdd(&g_S[gm], s);
        }
    }
}

// ---------------- final: cost = mean(log(S) - target_logit) ----------------
__global__ void k_final(float* __restrict__ out) {
    __shared__ float red[256];
    int tid = threadIdx.x;
    float acc = 0.f;
    for (int rr = tid; rr < kM; rr += 256) acc += logf(g_S[rr]) - g_TL[rr];
    red[tid] = acc;
    __syncthreads();
    for (int s = 128; s > 0; s >>= 1) {
        if (tid < s) red[tid] += red[tid + s];
        __syncthreads();
    }
    if (tid == 0) out[0] = red[0] / (float)kM;
}

// ---------------- launch ----------------------------------------------------
extern "C" void kernel_launch(void* const* d_in, const int* in_sizes, int n_in,
                              void* d_out, int out_size) {
    const int*   input_data = (const int*)d_in[0];
    const int*   targets    = (const int*)d_in[1];
    const float* emb        = (const float*)d_in[2];
    const float* W0         = (const float*)d_in[3];
    const float* b0         = (const float*)d_in[4];
    const float* W1         = (const float*)d_in[5];
    const float* b1         = (const float*)d_in[6];
    const float* sw         = (const float*)d_in[7];
    const float* sb         = (const float*)d_in[8];
    float* out = (float*)d_out;

    const int pipe_smem = (32 * 264 + 32 * 540 + 2 * 16 * 260) * 4;   // 136192 B
    const int gemm_smem = (2 * 256 * 36 + 2 * 32 * 136) * 4;          // 108544 B
    cudaFuncSetAttribute(k_lstm_pipe, cudaFuncAttributeMaxDynamicSharedMemorySize, pipe_smem);
    cudaFuncSetAttribute(k_gemm_zx_tf32, cudaFuncAttributeMaxDynamicSharedMemorySize, gemm_smem);
    cudaFuncSetAttribute(k_logits_tf32, cudaFuncAttributeMaxDynamicSharedMemorySize, gemm_smem);

    // k_lstm_pipe at launch index 3 — ncu's capture slot
    k_init<<<64, 256>>>();                                                   // 0
    k_gemm_zx_tf32<<<dim3(8, 32), 512, gemm_smem>>>(input_data, emb, W0, b0);// 1
    k_transpose<<<dim3(32, 16, 2), dim3(32, 8)>>>(W0, W1);                   // 2
    k_lstm_pipe<<<128, 512, pipe_smem>>>(b1);                                // 3
    k_logits_tf32<<<dim3(125, 32), 512, gemm_smem>>>(targets, sw, sb);       // 4
    k_final<<<1, 256>>>(out);                                                // 5
}

// round 7
// speedup vs baseline: 1.9228x; 1.9228x over previous
#include <cuda_runtime.h>
#include <math.h>
#include <stdint.h>

#define kB 64
#define kT 128
#define kU 256
#define kV 16000
#define kG 1024   /* 4*U */
#define kM 8192   /* B*T */

// ---------------- scratch (device globals; no allocation allowed) ----------
__device__ __align__(16) float g_Z0x[kT * kB * kG];
__device__ __align__(16) float g_H0[(kT + 1) * kB * kU];
__device__ __align__(16) float g_H1[(kT + 1) * kB * kU];
__device__ float g_S[kM];
__device__ float g_TL[kM];
__device__ unsigned g_bar[4];

__device__ __forceinline__ float sigmoidf_(float x) { return 1.f / (1.f + __expf(-x)); }

__device__ __forceinline__ uint32_t f2tf32(float x) {
    uint32_t u; asm("cvt.rna.tf32.f32 %0, %1;" : "=r"(u) : "f"(x)); return u;
}

__device__ __forceinline__ void mma_tf32(float* C,
    uint32_t a0, uint32_t a1, uint32_t a2, uint32_t a3, uint32_t b0, uint32_t b1) {
    asm volatile(
        "mma.sync.aligned.m16n8k8.row.col.f32.tf32.tf32.f32 "
        "{%0,%1,%2,%3}, {%4,%5,%6,%7}, {%8,%9}, {%0,%1,%2,%3};\n"
        : "+f"(C[0]), "+f"(C[1]), "+f"(C[2]), "+f"(C[3])
        : "r"(a0), "r"(a1), "r"(a2), "r"(a3), "r"(b0), "r"(b1));
}

__global__ void k_dummy() {}

// ---------------- init: zero states + sums + barriers -----------------------
__global__ void k_init() {
    int i = blockIdx.x * 256 + threadIdx.x;
    if (i < kB * kU) { g_H0[i] = 0.f; g_H1[i] = 0.f; }
    if (i < kM) g_S[i] = 0.f;
    if (i < 4) g_bar[i] = 0u;
}

// ---------------- Zx GEMM (tf32 mma, staged cvt): Z0 = emb[idx] @ W0x + b0 --
__global__ __launch_bounds__(512) void k_gemm_zx_tf32(
    const int* __restrict__ input_data, const float* __restrict__ emb,
    const float* __restrict__ W, const float* __restrict__ bias) {
    extern __shared__ uint32_t sm[];
    uint32_t* As = sm;                   // 2 buffers of 256x36 (tf32 bits)
    uint32_t* Bs = sm + 2 * 256 * 36;    // 2 buffers of 32x136
    __shared__ const float* rowp[256];
    float* Z = g_Z0x;
    const int tid = threadIdx.x;
    const int lane = tid & 31;
    const int w = tid >> 5;
    const int warpM = w & 7;
    const int warpN = w >> 3;
    const int m0 = blockIdx.y * 256;
    const int n0 = blockIdx.x * 128;
    const int r = lane >> 2, cq = lane & 3;

    if (tid < 256) {
        int m = m0 + tid;
        int t = m >> 6, b = m & 63;
        rowp[tid] = emb + (size_t)input_data[b * kT + t] * kU;
    }
    __syncthreads();

    float acc[2][8][4];
#pragma unroll
    for (int i = 0; i < 2; i++)
#pragma unroll
        for (int j = 0; j < 8; j++)
#pragma unroll
            for (int k = 0; k < 4; k++) acc[i][j][k] = 0.f;

    float4 ra[4], rb[2];
    auto loadG = [&](int kc) {
#pragma unroll
        for (int p = 0; p < 4; p++) {
            int e = p * 512 + tid;
            ra[p] = *(const float4*)&rowp[e >> 3][kc * 32 + (e & 7) * 4];
        }
#pragma unroll
        for (int p = 0; p < 2; p++) {
            int e = p * 512 + tid;
            rb[p] = *(const float4*)&W[(size_t)(kc * 32 + (e >> 5)) * kG + n0 + (e & 31) * 4];
        }
    };
    auto storeS = [&](int buf) {
        uint32_t* Ab = As + buf * 256 * 36;
        uint32_t* Bb = Bs + buf * 32 * 136;
#pragma unroll
        for (int p = 0; p < 4; p++) {
            int e = p * 512 + tid;
            uint4 v = make_uint4(f2tf32(ra[p].x), f2tf32(ra[p].y), f2tf32(ra[p].z), f2tf32(ra[p].w));
            *(uint4*)&Ab[(e >> 3) * 36 + (e & 7) * 4] = v;
        }
#pragma unroll
        for (int p = 0; p < 2; p++) {
            int e = p * 512 + tid;
            uint4 v = make_uint4(f2tf32(rb[p].x), f2tf32(rb[p].y), f2tf32(rb[p].z), f2tf32(rb[p].w));
            *(uint4*)&Bb[(e >> 5) * 136 + (e & 31) * 4] = v;
        }
    };

    loadG(0);
    storeS(0);
    __syncthreads();

    for (int kc = 0; kc < 8; kc++) {
        int buf = kc & 1;
        if (kc < 7) loadG(kc + 1);
        const uint32_t* Ab = As + buf * 256 * 36;
        const uint32_t* Bb = Bs + buf * 32 * 136;
#pragma unroll
        for (int kk = 0; kk < 4; kk++) {
            uint32_t af[2][4];
#pragma unroll
            for (int mi = 0; mi < 2; mi++) {
                const uint32_t* ap = &Ab[(warpM * 32 + mi * 16 + r) * 36 + kk * 8 + cq];
                af[mi][0] = ap[0];
                af[mi][1] = ap[8 * 36];
                af[mi][2] = ap[4];
                af[mi][3] = ap[8 * 36 + 4];
            }
#pragma unroll
            for (int ni = 0; ni < 8; ni++) {
                const uint32_t* bp = &Bb[(kk * 8 + cq) * 136 + warpN * 64 + ni * 8 + r];
                uint32_t b0 = bp[0];
                uint32_t b1 = bp[4 * 136];
#pragma unroll
                for (int mi = 0; mi < 2; mi++)
                    mma_tf32(acc[mi][ni], af[mi][0], af[mi][1], af[mi][2], af[mi][3], b0, b1);
            }
        }
        if (kc < 7) { storeS(buf ^ 1); __syncthreads(); }
    }

#pragma unroll
    for (int ni = 0; ni < 8; ni++) {
        int col = n0 + warpN * 64 + ni * 8 + cq * 2;
        float2 bb = *(const float2*)&bias[col];
#pragma unroll
        for (int mi = 0; mi < 2; mi++) {
            int gm = m0 + warpM * 32 + mi * 16 + r;
            *(float2*)&Z[(size_t)gm * kG + col] =
                make_float2(acc[mi][ni][0] + bb.x, acc[mi][ni][1] + bb.y);
            *(float2*)&Z[(size_t)(gm + 8) * kG + col] =
                make_float2(acc[mi][ni][2] + bb.x, acc[mi][ni][3] + bb.y);
        }
    }
}

// ---------------- pipelined 2-layer persistent LSTM, tensor-core step ------
// 128 blocks = 4 row-groups (16 rows) x 32 u-blocks (8 u). 512 threads.
// Warps 0..7: L0 k-slice ksl=w (32 k);  warps 8..15: L1 k-slice (64 k of 512).
// Weights live in REGISTERS as tf32 B-fragments (loaded once from W0/W1).
// h streams from smem as A-fragments, hi+lo tf32 split (~fp32 precision).
// Column index within block: c = u*4 + g  (gates contiguous for epilogue).
__global__ __launch_bounds__(512) void k_lstm_pipe(
    const float* __restrict__ W0, const float* __restrict__ W1,
    const float* __restrict__ b1v) {
    extern __shared__ float sms[];
    float* h0hi = sms;                  // 16 x 260
    float* h0lo = h0hi + 16 * 260;
    float* h1hi = h0lo + 16 * 260;
    float* h1lo = h1hi + 16 * 260;
    float* p0   = h1lo + 16 * 260;      // 8 x 16 x 36
    float* p1   = p0 + 8 * 16 * 36;

    const int tid = threadIdx.x;
    const int bx = blockIdx.x;
    const int rg = bx >> 5, ub = bx & 31;
    const int r0 = rg * 16;
    const int w = tid >> 5, lane = tid & 31;
    const int r = lane >> 2, cq = lane & 3;
    const int isL1 = (w >= 8);
    const int ksl = w & 7;

    // ---- load this warp's weight B-fragments into registers (once) ----
    uint32_t Bf[8][4][2];
    {
        const float* Wsrc = isL1 ? W1 : (W0 + (size_t)kU * kG);
        const int kstep = isL1 ? 64 : 32;
        const int nkt = isL1 ? 8 : 4;
#pragma unroll
        for (int kt = 0; kt < 8; kt++) {
            if (kt < nkt) {
                int kg = ksl * kstep + kt * 8 + cq;
#pragma unroll
                for (int nt = 0; nt < 4; nt++) {
                    int c = nt * 8 + r;
                    int gcol = (c & 3) * kU + ub * 8 + (c >> 2);
                    Bf[kt][nt][0] = f2tf32(Wsrc[(size_t)kg * kG + gcol]);
                    Bf[kt][nt][1] = f2tf32(Wsrc[(size_t)(kg + 4) * kG + gcol]);
                }
            }
        }
    }
    // A-fragment source pointers + k base for this warp
    const uint32_t* Ahi;
    const uint32_t* Alo;
    int kbase;
    if (!isL1)          { Ahi = (const uint32_t*)h0hi; Alo = (const uint32_t*)h0lo; kbase = ksl * 32; }
    else if (ksl < 4)   { Ahi = (const uint32_t*)h0hi; Alo = (const uint32_t*)h0lo; kbase = ksl * 64; }
    else                { Ahi = (const uint32_t*)h1hi; Alo = (const uint32_t*)h1lo; kbase = ksl * 64 - 256; }
    const int nkt = isL1 ? 8 : 4;
    float* pp = isL1 ? p1 : p0;

    // ---- zero h smem (initial state = 0; zeros are valid tf32) ----
    for (int i = tid; i < 4 * 16 * 260; i += 512) sms[i] = 0.f;
    __syncthreads();

    // epilogue thread state (tid < 128): (r8, u8)
    const int r8 = tid >> 3, u8 = tid & 7;
    const int u0e = ub * 8 + u8;
    float c0 = 0.f, c1 = 0.f;
    float b1g[4];
    if (tid < 128) {
#pragma unroll
        for (int g = 0; g < 4; g++) b1g[g] = b1v[g * kU + u0e];
    }

    for (int t = 0; t <= kT; t++) {
        // prefetch this step's z0x gates (epilogue threads)
        float z0g[4];
        if (tid < 128 && t < kT) {
#pragma unroll
            for (int g = 0; g < 4; g++)
                z0g[g] = __ldg(&g_Z0x[(size_t)t * kB * kG + (size_t)(r0 + r8) * kG + g * kU + u0e]);
        }

        // ---- mma phase ----
        float C[4][4];
#pragma unroll
        for (int nt = 0; nt < 4; nt++)
#pragma unroll
            for (int j = 0; j < 4; j++) C[nt][j] = 0.f;

        const bool active = isL1 ? (t >= 1) : (t < kT);
        if (active) {
#pragma unroll
            for (int kt = 0; kt < 8; kt++) {
                if (kt < nkt) {
                    int ka = kbase + kt * 8 + cq;
                    uint32_t ah0 = Ahi[r * 260 + ka];
                    uint32_t ah1 = Ahi[(r + 8) * 260 + ka];
                    uint32_t ah2 = Ahi[r * 260 + ka + 4];
                    uint32_t ah3 = Ahi[(r + 8) * 260 + ka + 4];
                    uint32_t al0 = Alo[r * 260 + ka];
                    uint32_t al1 = Alo[(r + 8) * 260 + ka];
                    uint32_t al2 = Alo[r * 260 + ka + 4];
                    uint32_t al3 = Alo[(r + 8) * 260 + ka + 4];
#pragma unroll
                    for (int nt = 0; nt < 4; nt++) {
                        mma_tf32(C[nt], ah0, ah1, ah2, ah3, Bf[kt][nt][0], Bf[kt][nt][1]);
                        mma_tf32(C[nt], al0, al1, al2, al3, Bf[kt][nt][0], Bf[kt][nt][1]);
                    }
                }
            }
        }
        // store partials [ksl][16][36]
#pragma unroll
        for (int nt = 0; nt < 4; nt++) {
            *(float2*)&pp[(ksl * 16 + r) * 36 + nt * 8 + 2 * cq] = make_float2(C[nt][0], C[nt][1]);
            *(float2*)&pp[(ksl * 16 + r + 8) * 36 + nt * 8 + 2 * cq] = make_float2(C[nt][2], C[nt][3]);
        }
        __syncthreads();

        // ---- epilogue: gates for (r8, u8) ----
        if (tid < 128) {
            if (t < kT) {
                float4 s = make_float4(0.f, 0.f, 0.f, 0.f);
#pragma unroll
                for (int k = 0; k < 8; k++) {
                    float4 p = *(const float4*)&p0[(k * 16 + r8) * 36 + u8 * 4];
                    s.x += p.x; s.y += p.y; s.z += p.z; s.w += p.w;
                }
                float zi = z0g[0] + s.x, zj = z0g[1] + s.y;
                float zf = z0g[2] + s.z, zo = z0g[3] + s.w;
                float inj = sigmoidf_(zi) * tanhf(zj);
                c0 = c0 * sigmoidf_(zf + 1.f) + inj;     // FORGET_BIAS = 1
                g_H0[(size_t)(t + 1) * kB * kU + (size_t)(r0 + r8) * kU + u0e] =
                    tanhf(c0) * sigmoidf_(zo);
            }
            if (t >= 1) {
                float4 s = make_float4(0.f, 0.f, 0.f, 0.f);
#pragma unroll
                for (int k = 0; k < 8; k++) {
                    float4 p = *(const float4*)&p1[(k * 16 + r8) * 36 + u8 * 4];
                    s.x += p.x; s.y += p.y; s.z += p.z; s.w += p.w;
                }
                float zi = b1g[0] + s.x, zj = b1g[1] + s.y;
                float zf = b1g[2] + s.z, zo = b1g[3] + s.w;
                float inj = sigmoidf_(zi) * tanhf(zj);
                c1 = c1 * sigmoidf_(zf + 1.f) + inj;
                g_H1[(size_t)t * kB * kU + (size_t)(r0 + r8) * kU + u0e] =
                    tanhf(c1) * sigmoidf_(zo);
            }
        }

        // ---- barrier over the 32 blocks of this row-group + h reload ----
        if (t < kT) {
            __syncthreads();
            if (tid == 0) {
                asm volatile("red.release.gpu.global.add.u32 [%0], %1;"
                             :: "l"(&g_bar[rg]), "r"(1u) : "memory");
                unsigned goal = (unsigned)(t + 1) * 32u;
                unsigned v;
                do {
                    asm volatile("ld.acquire.gpu.u32 %0, [%1];" : "=r"(v) : "l"(&g_bar[rg]));
                } while (v < goal);
            }
            __syncthreads();
            // reload h0 slot t+1 and h1 slot t; split into tf32 hi/lo
            const int rr = tid >> 5, kq = (tid & 31) * 8;
            const int so = rr * 260 + kq;
            {
                const float* src = &g_H0[(size_t)(t + 1) * kB * kU + (size_t)(r0 + rr) * kU + kq];
                float4 a = *(const float4*)src;
                float4 b = *(const float4*)(src + 4);
                float4 hi0, lo0, hi1, lo1;
                hi0.x = __uint_as_float(f2tf32(a.x)); lo0.x = __uint_as_float(f2tf32(a.x - hi0.x));
                hi0.y = __uint_as_float(f2tf32(a.y)); lo0.y = __uint_as_float(f2tf32(a.y - hi0.y));
                hi0.z = __uint_as_float(f2tf32(a.z)); lo0.z = __uint_as_float(f2tf32(a.z - hi0.z));
                hi0.w = __uint_as_float(f2tf32(a.w)); lo0.w = __uint_as_float(f2tf32(a.w - hi0.w));
                hi1.x = __uint_as_float(f2tf32(b.x)); lo1.x = __uint_as_float(f2tf32(b.x - hi1.x));
                hi1.y = __uint_as_float(f2tf32(b.y)); lo1.y = __uint_as_float(f2tf32(b.y - hi1.y));
                hi1.z = __uint_as_float(f2tf32(b.z)); lo1.z = __uint_as_float(f2tf32(b.z - hi1.z));
                hi1.w = __uint_as_float(f2tf32(b.w)); lo1.w = __uint_as_float(f2tf32(b.w - hi1.w));
                *(float4*)&h0hi[so] = hi0; *(float4*)&h0hi[so + 4] = hi1;
                *(float4*)&h0lo[so] = lo0; *(float4*)&h0lo[so + 4] = lo1;
            }
            {
                const float* src = &g_H1[(size_t)t * kB * kU + (size_t)(r0 + rr) * kU + kq];
                float4 a = *(const float4*)src;
                float4 b = *(const float4*)(src + 4);
                float4 hi0, lo0, hi1, lo1;
                hi0.x = __uint_as_float(f2tf32(a.x)); lo0.x = __uint_as_float(f2tf32(a.x - hi0.x));
                hi0.y = __uint_as_float(f2tf32(a.y)); lo0.y = __uint_as_float(f2tf32(a.y - hi0.y));
                hi0.z = __uint_as_float(f2tf32(a.z)); lo0.z = __uint_as_float(f2tf32(a.z - hi0.z));
                hi0.w = __uint_as_float(f2tf32(a.w)); lo0.w = __uint_as_float(f2tf32(a.w - hi0.w));
                hi1.x = __uint_as_float(f2tf32(b.x)); lo1.x = __uint_as_float(f2tf32(b.x - hi1.x));
                hi1.y = __uint_as_float(f2tf32(b.y)); lo1.y = __uint_as_float(f2tf32(b.y - hi1.y));
                hi1.z = __uint_as_float(f2tf32(b.z)); lo1.z = __uint_as_float(f2tf32(b.z - hi1.z));
                hi1.w = __uint_as_float(f2tf32(b.w)); lo1.w = __uint_as_float(f2tf32(b.w - hi1.w));
                *(float4*)&h1hi[so] = hi0; *(float4*)&h1hi[so + 4] = hi1;
                *(float4*)&h1lo[so] = lo0; *(float4*)&h1lo[so + 4] = lo1;
            }
            __syncthreads();
        }
    }
}

// ---------------- fused logits GEMM (tf32 mma, staged cvt) -----------------
__global__ __launch_bounds__(512) void k_logits_tf32(
    const int* __restrict__ targets, const float* __restrict__ SW,
    const float* __restrict__ sb) {
    extern __shared__ uint32_t sm[];
    uint32_t* As = sm;                   // 2 buffers of 256x36
    uint32_t* Bs = sm + 2 * 256 * 36;    // 2 buffers of 32x136
    const float* __restrict__ A = g_H1 + kB * kU;
    const int tid = threadIdx.x;
    const int lane = tid & 31;
    const int w = tid >> 5;
    const int warpM = w & 7;
    const int warpN = w >> 3;
    const int m0 = blockIdx.y * 256;
    const int n0 = blockIdx.x * 128;
    const int r = lane >> 2, cq = lane & 3;

    float acc[2][8][4];
#pragma unroll
    for (int i = 0; i < 2; i++)
#pragma unroll
        for (int j = 0; j < 8; j++)
#pragma unroll
            for (int k = 0; k < 4; k++) acc[i][j][k] = 0.f;

    float4 ra[4], rb[2];
    auto loadG = [&](int kc) {
#pragma unroll
        for (int p = 0; p < 4; p++) {
            int e = p * 512 + tid;
            ra[p] = *(const float4*)&A[(size_t)(m0 + (e >> 3)) * kU + kc * 32 + (e & 7) * 4];
        }
#pragma unroll
        for (int p = 0; p < 2; p++) {
            int e = p * 512 + tid;
            rb[p] = *(const float4*)&SW[(size_t)(kc * 32 + (e >> 5)) * kV + n0 + (e & 31) * 4];
        }
    };
    auto storeS = [&](int buf) {
        uint32_t* Ab = As + buf * 256 * 36;
        uint32_t* Bb = Bs + buf * 32 * 136;
#pragma unroll
        for (int p = 0; p < 4; p++) {
            int e = p * 512 + tid;
            uint4 v = make_uint4(f2tf32(ra[p].x), f2tf32(ra[p].y), f2tf32(ra[p].z), f2tf32(ra[p].w));
            *(uint4*)&Ab[(e >> 3) * 36 + (e & 7) * 4] = v;
        }
#pragma unroll
        for (int p = 0; p < 2; p++) {
            int e = p * 512 + tid;
            uint4 v = make_uint4(f2tf32(rb[p].x), f2tf32(rb[p].y), f2tf32(rb[p].z), f2tf32(rb[p].w));
            *(uint4*)&Bb[(e >> 5) * 136 + (e & 31) * 4] = v;
        }
    };

    loadG(0);
    storeS(0);
    __syncthreads();

    for (int kc = 0; kc < 8; kc++) {
        int buf = kc & 1;
        if (kc < 7) loadG(kc + 1);
        const uint32_t* Ab = As + buf * 256 * 36;
        const uint32_t* Bb = Bs + buf * 32 * 136;
#pragma unroll
        for (int kk = 0; kk < 4; kk++) {
            uint32_t af[2][4];
#pragma unroll
            for (int mi = 0; mi < 2; mi++) {
                const uint32_t* ap = &Ab[(warpM * 32 + mi * 16 + r) * 36 + kk * 8 + cq];
                af[mi][0] = ap[0];
                af[mi][1] = ap[8 * 36];
                af[mi][2] = ap[4];
                af[mi][3] = ap[8 * 36 + 4];
            }
#pragma unroll
            for (int ni = 0; ni < 8; ni++) {
                const uint32_t* bp = &Bb[(kk * 8 + cq) * 136 + warpN * 64 + ni * 8 + r];
                uint32_t b0 = bp[0];
                uint32_t b1 = bp[4 * 136];
#pragma unroll
                for (int mi = 0; mi < 2; mi++)
                    mma_tf32(acc[mi][ni], af[mi][0], af[mi][1], af[mi][2], af[mi][3], b0, b1);
            }
        }
        if (kc < 7) { storeS(buf ^ 1); __syncthreads(); }
    }

#pragma unroll
    for (int mi = 0; mi < 2; mi++) {
#pragma unroll
        for (int hh = 0; hh < 2; hh++) {
            int gm = m0 + warpM * 32 + mi * 16 + r + 8 * hh;
            int tt = gm >> 6, bb = gm & 63;
            int tg = targets[bb * kT + tt];
            float s = 0.f;
#pragma unroll
            for (int ni = 0; ni < 8; ni++) {
                int col = n0 + warpN * 64 + ni * 8 + cq * 2;
                float l0 = acc[mi][ni][hh * 2 + 0] + sb[col];
                float l1 = acc[mi][ni][hh * 2 + 1] + sb[col + 1];
                if (col == tg) g_TL[gm] = l0;
                if (col + 1 == tg) g_TL[gm] = l1;
                s += __expf(l0) + __expf(l1);
            }
            s += __shfl_xor_sync(0xffffffffu, s, 1);
            s += __shfl_xor_sync(0xffffffffu, s, 2);
            if (cq == 0) atomicAdd(&g_S[gm], s);
        }
    }
}

// ---------------- final: cost = mean(log(S) - target_logit) ----------------
__global__ void k_final(float* __restrict__ out) {
    __shared__ float red[256];
    int tid = threadIdx.x;
    float acc = 0.f;
    for (int rr = tid; rr < kM; rr += 256) acc += logf(g_S[rr]) - g_TL[rr];
    red[tid] = acc;
    __syncthreads();
    for (int s = 128; s > 0; s >>= 1) {
        if (tid < s) red[tid] += red[tid + s];
        __syncthreads();
    }
    if (tid == 0) out[0] = red[0] / (float)kM;
}

// ---------------- launch ----------------------------------------------------
extern "C" void kernel_launch(void* const* d_in, const int* in_sizes, int n_in,
                              void* d_out, int out_size) {
    const int*   input_data = (const int*)d_in[0];
    const int*   targets    = (const int*)d_in[1];
    const float* emb        = (const float*)d_in[2];
    const float* W0         = (const float*)d_in[3];
    const float* b0         = (const float*)d_in[4];
    const float* W1         = (const float*)d_in[5];
    const float* b1         = (const float*)d_in[6];
    const float* sw         = (const float*)d_in[7];
    const float* sb         = (const float*)d_in[8];
    float* out = (float*)d_out;

    const int pipe_smem = (4 * 16 * 260 + 2 * 8 * 16 * 36) * 4;   // 103424 B
    const int gemm_smem = (2 * 256 * 36 + 2 * 32 * 136) * 4;      // 108544 B
    cudaFuncSetAttribute(k_lstm_pipe, cudaFuncAttributeMaxDynamicSharedMemorySize, pipe_smem);
    cudaFuncSetAttribute(k_gemm_zx_tf32, cudaFuncAttributeMaxDynamicSharedMemorySize, gemm_smem);
    cudaFuncSetAttribute(k_logits_tf32, cudaFuncAttributeMaxDynamicSharedMemorySize, gemm_smem);

    // k_lstm_pipe at launch index 3 — ncu's capture slot
    k_init<<<64, 256>>>();                                                    // 0
    k_gemm_zx_tf32<<<dim3(8, 32), 512, gemm_smem>>>(input_data, emb, W0, b0); // 1
    k_dummy<<<1, 32>>>();                                                     // 2
    k_lstm_pipe<<<128, 512, pipe_smem>>>(W0, W1, b1);                         // 3
    k_logits_tf32<<<dim3(125, 32), 512, gemm_smem>>>(targets, sw, sb);        // 4
    k_final<<<1, 256>>>(out);                                                 // 5
}